// round 4
// baseline (speedup 1.0000x reference)
#include <cuda_runtime.h>
#include <cstdint>

#define NN 50000
#define HH 64
#define NEE 250000

typedef unsigned long long ull;

// ---------------- scratch (device globals; no runtime allocation) ----------------
// Only edge types {0,1,3,5,7} are ever used -> index by t, max 7 -> size 8.
__device__ __align__(16) float g_Q[8][NN * HH];
__device__ __align__(16) float g_K[8][NN * HH];
__device__ __align__(16) float g_V[8][NN * HH];
__device__ __align__(16) float g_O1[NN * HH];    // layer-1 output, node type 1
__device__ __align__(16) float g_O2[NN * HH];    // layer-1 output, node type 2
__device__ __align__(16) float g_OUT2[NN * HH];  // layer-2 output, node type 2
__device__ __align__(16) unsigned g_m[8][NN];    // per-pass softmax max (ordered-uint)
__device__ __align__(16) float g_den[8][NN];     // per-pass softmax denom
__device__ __align__(16) float g_alpha[8][NEE];  // per-pass raw attention logits

// ---------------- tables ----------------
__constant__ int c_src[9] = {0, 0, 0, 1, 1, 1, 2, 2, 3};
__constant__ int c_dst[9] = {1, 2, 3, 2, 3, 1, 3, 2, 3};
__constant__ int c_l1t[5] = {0, 1, 3, 5, 7};  // layer-1 live edge types
__constant__ int c_l2t[3] = {1, 3, 7};        // layer-2 live edge types
__constant__ int c_p2t[8] = {0, 1, 3, 5, 7, 1, 3, 7};  // pass -> edge type
__constant__ int c_p2l[8] = {0, 0, 0, 0, 0, 1, 1, 1};  // pass -> layer
__constant__ int c_p2o[8] = {0, 1, 1, 0, 1, 2, 2, 2};  // pass -> out buf (0=O1,1=O2,2=OUT2)

// ---------------- helpers ----------------
__device__ __forceinline__ ull pack2(float x, float y) {
    ull r; asm("mov.b64 %0, {%1, %2};" : "=l"(r) : "f"(x), "f"(y)); return r;
}
__device__ __forceinline__ void unpack2(ull v, float& x, float& y) {
    asm("mov.b64 {%0, %1}, %2;" : "=f"(x), "=f"(y) : "l"(v));
}
__device__ __forceinline__ void fma2(ull& a, ull x, ull w) {
    asm("fma.rn.f32x2 %0, %1, %2, %0;" : "+l"(a) : "l"(x), "l"(w));
}
__device__ __forceinline__ void redv4(float* p, float x, float y, float z, float w) {
    asm volatile("red.global.add.v4.f32 [%0], {%1,%2,%3,%4};"
                 :: "l"(p), "f"(x), "f"(y), "f"(z), "f"(w) : "memory");
}
// order-preserving float<->uint map (monotone; 0 is below every real value)
__device__ __forceinline__ unsigned ordf(float f) {
    unsigned u = __float_as_uint(f);
    return (u & 0x80000000u) ? ~u : (u | 0x80000000u);
}
__device__ __forceinline__ float deord(unsigned u) {
    return (u & 0x80000000u) ? __uint_as_float(u & 0x7fffffffu) : __uint_as_float(~u);
}

// ---------------- init: zero all accumulators (runs every replay) ----------------
__global__ void init_kernel() {
    int i = (blockIdx.x * 256 + threadIdx.x) * 4;
    float4 z = make_float4(0.f, 0.f, 0.f, 0.f);
    if (i < NN * HH) {
        *(float4*)(g_O1 + i) = z;
        *(float4*)(g_O2 + i) = z;
        *(float4*)(g_OUT2 + i) = z;
    }
    if (i < 8 * NN) {
        *(uint4*)(&g_m[0][0] + i) = make_uint4(0u, 0u, 0u, 0u);
        *(float4*)(&g_den[0][0] + i) = z;
    }
}

// ---------------- fused GEMM: all Q/K/V/skip projections of one layer ----------------
// grid: (ceil(N/128), njobs). job = 4*type_slot + role; role 0=Q,1=K,2=V,3=skip.
// 2 rows x 16 cols per thread, f32x2 FMA. smem = 16KB W + 32KB X^T = 48KB exactly.
__global__ void __launch_bounds__(256, 3) gemm_kernel(
    const float* __restrict__ x0, const float* __restrict__ x1,
    const float* __restrict__ x2, const float* __restrict__ x3,
    const float* __restrict__ Wq, const float* __restrict__ bq,
    const float* __restrict__ Wk, const float* __restrict__ bk,
    const float* __restrict__ Wv, const float* __restrict__ bv,
    const float* __restrict__ Ws, const float* __restrict__ bs,
    int layer)
{
    __shared__ __align__(16) float sW[64 * 64];
    __shared__ __align__(16) float sX[64 * 128];  // transposed: sX[k*128 + r]

    if (layer) { x1 = g_O1; x2 = g_O2; }  // layer-2 inputs are relu'd layer-1 outputs

    int job = blockIdx.y;
    int t = (layer == 0) ? c_l1t[job >> 2] : c_l2t[job >> 2];
    int role = job & 3;
    int s = c_src[t], d = c_dst[t];
    int insel = (role == 1 || role == 2) ? s : d;
    const float* X = (insel == 0) ? x0 : (insel == 1) ? x1 : (insel == 2) ? x2 : x3;
    int wo = layer * 9 + t;
    const float* W; const float* B;
    if (role == 0)      { W = Wq + wo * 4096; B = bq + wo * 64; }
    else if (role == 1) { W = Wk + wo * 4096; B = bk + wo * 64; }
    else if (role == 2) { W = Wv + wo * 4096; B = bv + wo * 64; }
    else                { W = Ws + wo * 4096; B = bs + wo * 64; }
    float* OUT;
    if (role == 0)      OUT = g_Q[t];
    else if (role == 1) OUT = g_K[t];
    else if (role == 2) OUT = g_V[t];
    else                OUT = layer ? g_OUT2 : (d == 1 ? g_O1 : g_O2);

    int tid = threadIdx.x;
    int row0 = blockIdx.x * 128;

    // stage W [64][64]
    for (int i = tid * 4; i < 4096; i += 1024)
        *(float4*)(sW + i) = *(const float4*)(W + i);
    // stage X tile transposed
    for (int i = tid; i < 128 * 16; i += 256) {
        int rl = i >> 4, kq = (i & 15) * 4;
        int r = row0 + rl;
        float4 v = make_float4(0.f, 0.f, 0.f, 0.f);
        if (r < NN) v = *(const float4*)(X + r * 64 + kq);
        sX[(kq + 0) * 128 + rl] = v.x;
        sX[(kq + 1) * 128 + rl] = v.y;
        sX[(kq + 2) * 128 + rl] = v.z;
        sX[(kq + 3) * 128 + rl] = v.w;
    }
    __syncthreads();

    int cg = tid & 3;   // column group: cols [cg*16, cg*16+16)
    int rg = tid >> 2;  // row group: rows rg*2, rg*2+1
    int c0 = cg * 16;

    ull acc0[8], acc1[8];
    const ull* B64 = (const ull*)(B + c0);
    #pragma unroll
    for (int j = 0; j < 8; j++) { acc0[j] = B64[j]; acc1[j] = acc0[j]; }

    #pragma unroll 8
    for (int k = 0; k < 64; k++) {
        float2 xv = *(const float2*)(sX + k * 128 + (rg << 1));
        ull xa = pack2(xv.x, xv.x);
        ull xb = pack2(xv.y, xv.y);
        const longlong2* wr = (const longlong2*)(sW + k * 64 + c0);
        #pragma unroll
        for (int q = 0; q < 4; q++) {
            longlong2 w = wr[q];
            fma2(acc0[2 * q + 0], xa, (ull)w.x);
            fma2(acc0[2 * q + 1], xa, (ull)w.y);
            fma2(acc1[2 * q + 0], xb, (ull)w.x);
            fma2(acc1[2 * q + 1], xb, (ull)w.y);
        }
    }

    int r0 = row0 + (rg << 1);
    if (role != 3) {
        if (r0 < NN) {
            ull* o = (ull*)(OUT + r0 * 64 + c0);
            #pragma unroll
            for (int j = 0; j < 8; j++) o[j] = acc0[j];
        }
        if (r0 + 1 < NN) {
            ull* o = (ull*)(OUT + (r0 + 1) * 64 + c0);
            #pragma unroll
            for (int j = 0; j < 8; j++) o[j] = acc1[j];
        }
    } else {
        if (r0 < NN) {
            float* o = OUT + r0 * 64 + c0;
            #pragma unroll
            for (int q = 0; q < 4; q++) {
                float a, b, c, dd;
                unpack2(acc0[2 * q], a, b); unpack2(acc0[2 * q + 1], c, dd);
                redv4(o + q * 4, a, b, c, dd);
            }
        }
        if (r0 + 1 < NN) {
            float* o = OUT + (r0 + 1) * 64 + c0;
            #pragma unroll
            for (int q = 0; q < 4; q++) {
                float a, b, c, dd;
                unpack2(acc1[2 * q], a, b); unpack2(acc1[2 * q + 1], c, dd);
                redv4(o + q * 4, a, b, c, dd);
            }
        }
    }
}

// ---------------- pass A: logits + segment max. 8 lanes per edge. ----------------
__global__ void __launch_bounds__(256) passA_kernel(
    const int* __restrict__ EI, const float* __restrict__ EA,
    const float* __restrict__ We, int pbase)
{
    int p = pbase + blockIdx.y;
    int t = c_p2t[p];
    __shared__ __align__(16) float sWe[128];
    if (threadIdx.x < 32)
        ((float4*)sWe)[threadIdx.x] = ((const float4*)(We + (c_p2l[p] * 9 + t) * 128))[threadIdx.x];
    __syncthreads();

    int lane = threadIdx.x & 7;
    int eid = blockIdx.x * 32 + (threadIdx.x >> 3);
    if (eid >= NEE) return;
    int src = EI[t * 2 * NEE + eid];
    int dst = EI[t * 2 * NEE + NEE + eid];
    float2 ea = *(const float2*)(EA + (size_t)t * NEE * 2 + eid * 2);

    const float4* Q4 = (const float4*)(g_Q[t] + dst * 64 + lane * 8);
    const float4* K4 = (const float4*)(g_K[t] + src * 64 + lane * 8);
    const float4* W0 = (const float4*)(sWe) + lane * 2;
    const float4* W1 = (const float4*)(sWe + 64) + lane * 2;

    float part = 0.f;
    #pragma unroll
    for (int c = 0; c < 2; c++) {
        float4 q = Q4[c], kk = K4[c], w0 = W0[c], w1 = W1[c];
        float kx = fmaf(ea.x, w0.x, fmaf(ea.y, w1.x, kk.x));
        float ky = fmaf(ea.x, w0.y, fmaf(ea.y, w1.y, kk.y));
        float kz = fmaf(ea.x, w0.z, fmaf(ea.y, w1.z, kk.z));
        float kw = fmaf(ea.x, w0.w, fmaf(ea.y, w1.w, kk.w));
        part = fmaf(q.x, kx, part);
        part = fmaf(q.y, ky, part);
        part = fmaf(q.z, kz, part);
        part = fmaf(q.w, kw, part);
    }
    part += __shfl_xor_sync(0xffffffffu, part, 1);
    part += __shfl_xor_sync(0xffffffffu, part, 2);
    part += __shfl_xor_sync(0xffffffffu, part, 4);
    if (lane == 0) {
        float alpha = part * 0.125f;  // 1/sqrt(64)
        g_alpha[p][eid] = alpha;
        atomicMax(&g_m[p][dst], ordf(alpha));
    }
}

// ---------------- pass B: segment sum of exp ----------------
__global__ void __launch_bounds__(256) passB_kernel(const int* __restrict__ EI, int pbase) {
    int p = pbase + blockIdx.y;
    int t = c_p2t[p];
    int eid = blockIdx.x * 256 + threadIdx.x;
    if (eid >= NEE) return;
    int dst = EI[t * 2 * NEE + NEE + eid];
    float a = g_alpha[p][eid];
    float m = deord(g_m[p][dst]);
    atomicAdd(&g_den[p][dst], __expf(a - m));
}

// ---------------- pass C: weighted aggregate into layer output ----------------
__global__ void __launch_bounds__(256) passC_kernel(
    const int* __restrict__ EI, const float* __restrict__ EA,
    const float* __restrict__ We, int pbase)
{
    int p = pbase + blockIdx.y;
    int t = c_p2t[p];
    __shared__ __align__(16) float sWe[128];
    if (threadIdx.x < 32)
        ((float4*)sWe)[threadIdx.x] = ((const float4*)(We + (c_p2l[p] * 9 + t) * 128))[threadIdx.x];
    __syncthreads();

    int lane = threadIdx.x & 7;
    int eid = blockIdx.x * 32 + (threadIdx.x >> 3);
    if (eid >= NEE) return;
    int src = EI[t * 2 * NEE + eid];
    int dst = EI[t * 2 * NEE + NEE + eid];
    float2 ea = *(const float2*)(EA + (size_t)t * NEE * 2 + eid * 2);

    float a = g_alpha[p][eid];
    float m = deord(g_m[p][dst]);
    float den = g_den[p][dst];
    float wgt = __expf(a - m) / (den + 1e-16f);

    int os = c_p2o[p];
    float* O = (os == 0) ? g_O1 : (os == 1) ? g_O2 : g_OUT2;
    const float4* V4 = (const float4*)(g_V[t] + src * 64 + lane * 8);
    const float4* W0 = (const float4*)(sWe) + lane * 2;
    const float4* W1 = (const float4*)(sWe + 64) + lane * 2;
    float* Or = O + dst * 64 + lane * 8;

    #pragma unroll
    for (int c = 0; c < 2; c++) {
        float4 v = V4[c], w0 = W0[c], w1 = W1[c];
        float vx = fmaf(ea.x, w0.x, fmaf(ea.y, w1.x, v.x)) * wgt;
        float vy = fmaf(ea.x, w0.y, fmaf(ea.y, w1.y, v.y)) * wgt;
        float vz = fmaf(ea.x, w0.z, fmaf(ea.y, w1.z, v.z)) * wgt;
        float vw = fmaf(ea.x, w0.w, fmaf(ea.y, w1.w, v.w)) * wgt;
        redv4(Or + c * 4, vx, vy, vz, vw);
    }
}

// ---------------- relu on layer-1 outputs ----------------
__global__ void relu_kernel() {
    int i = (blockIdx.x * 256 + threadIdx.x) * 4;
    if (i < NN * HH) {
        float4 a = *(float4*)(g_O1 + i);
        a.x = fmaxf(a.x, 0.f); a.y = fmaxf(a.y, 0.f);
        a.z = fmaxf(a.z, 0.f); a.w = fmaxf(a.w, 0.f);
        *(float4*)(g_O1 + i) = a;
        float4 b = *(float4*)(g_O2 + i);
        b.x = fmaxf(b.x, 0.f); b.y = fmaxf(b.y, 0.f);
        b.z = fmaxf(b.z, 0.f); b.w = fmaxf(b.w, 0.f);
        *(float4*)(g_O2 + i) = b;
    }
}

// ---------------- final: relu(OUT2) @ lin_W + lin_b. 8 lanes per row. ----------------
__global__ void __launch_bounds__(256) final_kernel(
    const float* __restrict__ linW, const float* __restrict__ linb, float* __restrict__ out)
{
    __shared__ __align__(16) float4 sLW[64];
    if (threadIdx.x < 64) sLW[threadIdx.x] = *(const float4*)(linW + threadIdx.x * 4);
    __syncthreads();
    int lane = threadIdx.x & 7;
    int row = blockIdx.x * 32 + (threadIdx.x >> 3);
    if (row >= NN) return;
    const float* X = g_OUT2 + row * 64 + lane * 8;
    float4 acc = make_float4(0.f, 0.f, 0.f, 0.f);
    #pragma unroll
    for (int c = 0; c < 8; c++) {
        float x = fmaxf(X[c], 0.f);
        float4 wv = sLW[lane * 8 + c];
        acc.x = fmaf(x, wv.x, acc.x);
        acc.y = fmaf(x, wv.y, acc.y);
        acc.z = fmaf(x, wv.z, acc.z);
        acc.w = fmaf(x, wv.w, acc.w);
    }
    #pragma unroll
    for (int off = 1; off < 8; off <<= 1) {
        acc.x += __shfl_xor_sync(0xffffffffu, acc.x, off);
        acc.y += __shfl_xor_sync(0xffffffffu, acc.y, off);
        acc.z += __shfl_xor_sync(0xffffffffu, acc.z, off);
        acc.w += __shfl_xor_sync(0xffffffffu, acc.w, off);
    }
    if (lane == 0) {
        float4 b = *(const float4*)linb;
        acc.x += b.x; acc.y += b.y; acc.z += b.z; acc.w += b.w;
        *(float4*)(out + row * 4) = acc;
    }
}

// ---------------- launcher ----------------
extern "C" void kernel_launch(void* const* d_in, const int* in_sizes, int n_in,
                              void* d_out, int out_size) {
    (void)in_sizes; (void)n_in; (void)out_size;
    const float* x0 = (const float*)d_in[0];
    const float* x1 = (const float*)d_in[1];
    const float* x2 = (const float*)d_in[2];
    const float* x3 = (const float*)d_in[3];
    const int*   EI = (const int*)d_in[4];
    const float* EA = (const float*)d_in[5];
    const float* Wq = (const float*)d_in[6];
    const float* bq = (const float*)d_in[7];
    const float* Wk = (const float*)d_in[8];
    const float* bk = (const float*)d_in[9];
    const float* Wv = (const float*)d_in[10];
    const float* bv = (const float*)d_in[11];
    const float* We = (const float*)d_in[12];
    const float* Ws = (const float*)d_in[13];
    const float* bs = (const float*)d_in[14];
    const float* lW = (const float*)d_in[15];
    const float* lb = (const float*)d_in[16];
    float* out = (float*)d_out;

    const int ROWB = (NN + 127) / 128;       // 391
    const int EB32 = (NEE + 31) / 32;        // 7813
    const int EB256 = (NEE + 255) / 256;     // 977

    init_kernel<<<3125, 256>>>();

    // ---- layer 1: 5 live edge types ----
    gemm_kernel<<<dim3(ROWB, 20), 256>>>(x0, x1, x2, x3, Wq, bq, Wk, bk, Wv, bv, Ws, bs, 0);
    passA_kernel<<<dim3(EB32, 5), 256>>>(EI, EA, We, 0);
    passB_kernel<<<dim3(EB256, 5), 256>>>(EI, 0);
    passC_kernel<<<dim3(EB32, 5), 256>>>(EI, EA, We, 0);
    relu_kernel<<<3125, 256>>>();

    // ---- layer 2: 3 live edge types (d==2 only) ----
    gemm_kernel<<<dim3(ROWB, 12), 256>>>(x0, x1, x2, x3, Wq, bq, Wk, bk, Wv, bv, Ws, bs, 1);
    passA_kernel<<<dim3(EB32, 3), 256>>>(EI, EA, We, 5);
    passB_kernel<<<dim3(EB256, 3), 256>>>(EI, 5);
    passC_kernel<<<dim3(EB32, 3), 256>>>(EI, EA, We, 5);

    final_kernel<<<(NN + 31) / 32, 256>>>(lW, lb, out);
}

// round 6
// speedup vs baseline: 1.7557x; 1.7557x over previous
#include <cuda_runtime.h>
#include <cstdint>
#include <math_constants.h>

#define NN 50000
#define HH 64
#define NEE 250000
#define NB 98            // ceil(NN/512)

typedef unsigned long long ull;

// ---------------- scratch (device globals; no runtime allocation) ----------------
// 5 live edge-type slots: t {0,1,3,5,7} -> slot {0,1,2,3,4}
__device__ __align__(16) float g_Q[5][NN * HH];
__device__ __align__(16) float g_K[5][NN * HH];
__device__ __align__(16) float g_V[5][NN * HH];
__device__ __align__(16) float g_O1[NN * HH];    // layer-1 output, node type 1
__device__ __align__(16) float g_O2[NN * HH];    // layer-1 output, node type 2
__device__ __align__(16) float g_OUT2[NN * HH];  // layer-2 output, node type 2
// CSR build scratch
__device__ __align__(16) unsigned g_cnt[5][NN];
__device__ __align__(16) unsigned g_ex[5][NN];
__device__ __align__(16) unsigned g_bs[5][NB];
__device__ __align__(16) unsigned g_bso[5][NB];
__device__ __align__(16) unsigned g_startv[5][NN];
__device__ __align__(16) unsigned g_cursor[5][NN];
__device__ __align__(16) int2     g_adj[5][NEE];  // (src, eid) per dst-sorted position

// ---------------- tables ----------------
__constant__ int c_src[9] = {0, 0, 0, 1, 1, 1, 2, 2, 3};
__constant__ int c_dst[9] = {1, 2, 3, 2, 3, 1, 3, 2, 3};
__constant__ int c_l1t[5] = {0, 1, 3, 5, 7};
__constant__ int c_l2t[3] = {1, 3, 7};
__constant__ int c_t2s[8] = {0, 1, 0, 2, 0, 3, 0, 4};
__constant__ int c_s2t[5] = {0, 1, 3, 5, 7};
__constant__ int c_p2t[8] = {0, 1, 3, 5, 7, 1, 3, 7};
__constant__ int c_p2s[8] = {0, 1, 2, 3, 4, 1, 2, 4};
__constant__ int c_p2l[8] = {0, 0, 0, 0, 0, 1, 1, 1};
__constant__ int c_p2o[8] = {0, 1, 1, 0, 1, 2, 2, 2};  // 0=O1, 1=O2, 2=OUT2

// ---------------- helpers ----------------
__device__ __forceinline__ void fma2(ull& a, ull x, ull w) {
    asm("fma.rn.f32x2 %0, %1, %2, %0;" : "+l"(a) : "l"(x), "l"(w));
}
__device__ __forceinline__ ull pack2(float x, float y) {
    ull r; asm("mov.b64 %0, {%1, %2};" : "=l"(r) : "f"(x), "f"(y)); return r;
}
__device__ __forceinline__ void unpack2(ull v, float& x, float& y) {
    asm("mov.b64 {%0, %1}, %2;" : "=f"(x), "=f"(y) : "l"(v));
}
__device__ __forceinline__ void redv4(float* p, float x, float y, float z, float w) {
    asm volatile("red.global.add.v4.f32 [%0], {%1,%2,%3,%4};"
                 :: "l"(p), "f"(x), "f"(y), "f"(z), "f"(w) : "memory");
}

// ---------------- init: zero accumulators + CSR counters (every replay) ----------------
__global__ void init_kernel() {
    int i = (blockIdx.x * 256 + threadIdx.x) * 4;
    float4 z = make_float4(0.f, 0.f, 0.f, 0.f);
    if (i < NN * HH) {
        *(float4*)(g_O1 + i) = z;
        *(float4*)(g_O2 + i) = z;
        *(float4*)(g_OUT2 + i) = z;
    }
    if (i < 5 * NN) *(uint4*)(&g_cnt[0][0] + i) = make_uint4(0u, 0u, 0u, 0u);
}

// ---------------- CSR build ----------------
__global__ void __launch_bounds__(256) count_kernel(const int* __restrict__ EI) {
    int slot = blockIdx.y, t = c_s2t[slot];
    int eid = blockIdx.x * 256 + threadIdx.x;
    if (eid >= NEE) return;
    int dst = EI[t * 2 * NEE + NEE + eid];
    atomicAdd(&g_cnt[slot][dst], 1u);
}

__global__ void __launch_bounds__(512) scan1_kernel() {
    int slot = blockIdx.y;
    int i = blockIdx.x * 512 + threadIdx.x;
    unsigned v = (i < NN) ? g_cnt[slot][i] : 0u;
    __shared__ unsigned s[512];
    s[threadIdx.x] = v;
    __syncthreads();
    #pragma unroll
    for (int off = 1; off < 512; off <<= 1) {
        unsigned t = (threadIdx.x >= off) ? s[threadIdx.x - off] : 0u;
        __syncthreads();
        s[threadIdx.x] += t;
        __syncthreads();
    }
    if (i < NN) g_ex[slot][i] = s[threadIdx.x] - v;
    if (threadIdx.x == 511) g_bs[slot][blockIdx.x] = s[511];
}

__global__ void __launch_bounds__(128) scan2_kernel() {
    int slot = blockIdx.x;
    unsigned v = (threadIdx.x < NB) ? g_bs[slot][threadIdx.x] : 0u;
    __shared__ unsigned s[128];
    s[threadIdx.x] = v;
    __syncthreads();
    #pragma unroll
    for (int off = 1; off < 128; off <<= 1) {
        unsigned t = (threadIdx.x >= off) ? s[threadIdx.x - off] : 0u;
        __syncthreads();
        s[threadIdx.x] += t;
        __syncthreads();
    }
    if (threadIdx.x < NB) g_bso[slot][threadIdx.x] = s[threadIdx.x] - v;
}

__global__ void __launch_bounds__(512) scan3_kernel() {
    int slot = blockIdx.y;
    int i = blockIdx.x * 512 + threadIdx.x;
    if (i < NN) {
        unsigned st = g_ex[slot][i] + g_bso[slot][blockIdx.x];
        g_startv[slot][i] = st;
        g_cursor[slot][i] = st;
    }
}

__global__ void __launch_bounds__(256) scatter_kernel(const int* __restrict__ EI) {
    int slot = blockIdx.y, t = c_s2t[slot];
    int eid = blockIdx.x * 256 + threadIdx.x;
    if (eid >= NEE) return;
    int src = EI[t * 2 * NEE + eid];
    int dst = EI[t * 2 * NEE + NEE + eid];
    unsigned pos = atomicAdd(&g_cursor[slot][dst], 1u);
    g_adj[slot][pos] = make_int2(src, eid);
}

// ---------------- fused GEMM: all Q/K/V/skip projections of one layer ----------------
// Thread computes rows {rg*2, rg*2+1}, 16 cols {cg*4 + q*16 + j}. f32x2 FMA.
// sX XOR-swizzled (r ^ (k&30)) to kill staging bank conflicts; W col layout
// (cg*4 + q*16) makes compute-loop W reads broadcast conflict-free.
__global__ void __launch_bounds__(256, 3) gemm_kernel(
    const float* __restrict__ x0, const float* __restrict__ x1,
    const float* __restrict__ x2, const float* __restrict__ x3,
    const float* __restrict__ Wq, const float* __restrict__ bq,
    const float* __restrict__ Wk, const float* __restrict__ bk,
    const float* __restrict__ Wv, const float* __restrict__ bv,
    const float* __restrict__ Ws, const float* __restrict__ bs,
    int layer)
{
    __shared__ __align__(16) float sW[64 * 64];
    __shared__ __align__(16) float sX[64 * 128];

    if (layer) { x1 = g_O1; x2 = g_O2; }

    int job = blockIdx.y;
    int t = (layer == 0) ? c_l1t[job >> 2] : c_l2t[job >> 2];
    int role = job & 3;
    int slot = c_t2s[t];
    int s = c_src[t], d = c_dst[t];
    int insel = (role == 1 || role == 2) ? s : d;
    const float* X = (insel == 0) ? x0 : (insel == 1) ? x1 : (insel == 2) ? x2 : x3;
    bool reluX = (layer != 0) && (insel != 0);  // layer-2 O1/O2 inputs need relu
    int wo = layer * 9 + t;
    const float* W; const float* B;
    if (role == 0)      { W = Wq + wo * 4096; B = bq + wo * 64; }
    else if (role == 1) { W = Wk + wo * 4096; B = bk + wo * 64; }
    else if (role == 2) { W = Wv + wo * 4096; B = bv + wo * 64; }
    else                { W = Ws + wo * 4096; B = bs + wo * 64; }
    float* OUT;
    if (role == 0)      OUT = g_Q[slot];
    else if (role == 1) OUT = g_K[slot];
    else if (role == 2) OUT = g_V[slot];
    else                OUT = layer ? g_OUT2 : (d == 1 ? g_O1 : g_O2);

    int tid = threadIdx.x;
    int row0 = blockIdx.x * 128;

    // stage W [64][64] (conflict-free)
    for (int i = tid * 4; i < 4096; i += 1024)
        *(float4*)(sW + i) = *(const float4*)(W + i);
    // stage X tile transposed with XOR swizzle
    for (int i = tid; i < 128 * 16; i += 256) {
        int rl = i >> 4, kq = (i & 15) * 4;
        int r = row0 + rl;
        float4 v = make_float4(0.f, 0.f, 0.f, 0.f);
        if (r < NN) v = *(const float4*)(X + (size_t)r * 64 + kq);
        if (reluX) {
            v.x = fmaxf(v.x, 0.f); v.y = fmaxf(v.y, 0.f);
            v.z = fmaxf(v.z, 0.f); v.w = fmaxf(v.w, 0.f);
        }
        sX[(kq + 0) * 128 + (rl ^ ((kq + 0) & 30))] = v.x;
        sX[(kq + 1) * 128 + (rl ^ ((kq + 1) & 30))] = v.y;
        sX[(kq + 2) * 128 + (rl ^ ((kq + 2) & 30))] = v.z;
        sX[(kq + 3) * 128 + (rl ^ ((kq + 3) & 30))] = v.w;
    }
    __syncthreads();

    int cg = tid & 3;   // col base cg*4; full set {cg*4 + q*16 + j}
    int rg = tid >> 2;  // rows rg*2, rg*2+1
    int c0 = cg * 4;

    ull acc0[8], acc1[8];
    #pragma unroll
    for (int q = 0; q < 4; q++) {
        const ull* Bq = (const ull*)(B + c0 + q * 16);
        acc0[2 * q] = Bq[0]; acc0[2 * q + 1] = Bq[1];
        acc1[2 * q] = acc0[2 * q]; acc1[2 * q + 1] = acc0[2 * q + 1];
    }

    #pragma unroll 8
    for (int k = 0; k < 64; k++) {
        float2 xv = *(const float2*)(sX + k * 128 + ((rg << 1) ^ (k & 30)));
        ull xa = pack2(xv.x, xv.x);
        ull xb = pack2(xv.y, xv.y);
        #pragma unroll
        for (int q = 0; q < 4; q++) {
            longlong2 w = *(const longlong2*)(sW + k * 64 + c0 + q * 16);
            fma2(acc0[2 * q + 0], xa, (ull)w.x);
            fma2(acc0[2 * q + 1], xa, (ull)w.y);
            fma2(acc1[2 * q + 0], xb, (ull)w.x);
            fma2(acc1[2 * q + 1], xb, (ull)w.y);
        }
    }

    int r0 = row0 + (rg << 1);
    if (role != 3) {
        if (r0 < NN) {
            float* o = OUT + (size_t)r0 * 64 + c0;
            #pragma unroll
            for (int q = 0; q < 4; q++) {
                *(ull*)(o + q * 16) = acc0[2 * q];
                *(ull*)(o + q * 16 + 2) = acc0[2 * q + 1];
            }
        }
        if (r0 + 1 < NN) {
            float* o = OUT + (size_t)(r0 + 1) * 64 + c0;
            #pragma unroll
            for (int q = 0; q < 4; q++) {
                *(ull*)(o + q * 16) = acc1[2 * q];
                *(ull*)(o + q * 16 + 2) = acc1[2 * q + 1];
            }
        }
    } else {
        if (r0 < NN) {
            float* o = OUT + (size_t)r0 * 64 + c0;
            #pragma unroll
            for (int q = 0; q < 4; q++) {
                float a, b, c, dd;
                unpack2(acc0[2 * q], a, b); unpack2(acc0[2 * q + 1], c, dd);
                redv4(o + q * 16, a, b, c, dd);
            }
        }
        if (r0 + 1 < NN) {
            float* o = OUT + (size_t)(r0 + 1) * 64 + c0;
            #pragma unroll
            for (int q = 0; q < 4; q++) {
                float a, b, c, dd;
                unpack2(acc1[2 * q], a, b); unpack2(acc1[2 * q + 1], c, dd);
                redv4(o + q * 16, a, b, c, dd);
            }
        }
    }
}

// ---------------- fused edge pass: per-dst online softmax + aggregate ----------------
// 8 lanes per dst, 32 dsts per block. One pass over CSR-sorted in-edges,
// software-pipelined one iteration deep (adj/EA prefetch).
__global__ void __launch_bounds__(256) fused_attn_kernel(
    const float* __restrict__ EA, const float* __restrict__ We, int pbase)
{
    int p = pbase + blockIdx.y;
    int t = c_p2t[p], slot = c_p2s[p];
    __shared__ __align__(16) float sWe[128];
    if (threadIdx.x < 32)
        ((float4*)sWe)[threadIdx.x] = ((const float4*)(We + (c_p2l[p] * 9 + t) * 128))[threadIdx.x];
    __syncthreads();

    int lane = threadIdx.x & 7;
    unsigned gmask = 0xFFu << (threadIdx.x & 24);
    int dst = blockIdx.x * 32 + (threadIdx.x >> 3);
    bool valid = dst < NN;
    int d0 = valid ? dst : 0;

    unsigned start = g_startv[slot][d0];
    unsigned end = (d0 == NN - 1) ? (unsigned)NEE : g_startv[slot][d0 + 1];
    if (!valid) end = start;

    float4 q0 = make_float4(0, 0, 0, 0), q1 = q0;
    if (valid) {
        const float4* Q4 = (const float4*)(g_Q[slot] + (size_t)d0 * 64 + lane * 8);
        q0 = Q4[0]; q1 = Q4[1];
    }
    float4 w0a = ((const float4*)sWe)[lane * 2];
    float4 w0b = ((const float4*)sWe)[lane * 2 + 1];
    float4 w1a = ((const float4*)(sWe + 64))[lane * 2];
    float4 w1b = ((const float4*)(sWe + 64))[lane * 2 + 1];

    const float2* EAt = (const float2*)EA + (size_t)t * NEE;
    const int2* adj = g_adj[slot];

    float m = -CUDART_INF_F, den = 0.f;
    float4 a0 = make_float4(0, 0, 0, 0), a1 = a0;

    // prefetch depth 1
    int2 se = make_int2(0, 0);
    float2 ea = make_float2(0.f, 0.f);
    if (start < end) { se = adj[start]; ea = EAt[se.y]; }

    for (unsigned j = start; j < end; ++j) {
        int2 cse = se;
        float2 cea = ea;
        const float4* K4 = (const float4*)(g_K[slot] + (size_t)cse.x * 64 + lane * 8);
        const float4* V4 = (const float4*)(g_V[slot] + (size_t)cse.x * 64 + lane * 8);
        float4 k0 = K4[0], k1 = K4[1];
        float4 v0 = V4[0], v1 = V4[1];
        if (j + 1 < end) { se = adj[j + 1]; ea = EAt[se.y]; }

        float4 e0, e1;
        e0.x = fmaf(cea.x, w0a.x, cea.y * w1a.x);
        e0.y = fmaf(cea.x, w0a.y, cea.y * w1a.y);
        e0.z = fmaf(cea.x, w0a.z, cea.y * w1a.z);
        e0.w = fmaf(cea.x, w0a.w, cea.y * w1a.w);
        e1.x = fmaf(cea.x, w0b.x, cea.y * w1b.x);
        e1.y = fmaf(cea.x, w0b.y, cea.y * w1b.y);
        e1.z = fmaf(cea.x, w0b.z, cea.y * w1b.z);
        e1.w = fmaf(cea.x, w0b.w, cea.y * w1b.w);

        float part;
        part = q0.x * (k0.x + e0.x);
        part = fmaf(q0.y, k0.y + e0.y, part);
        part = fmaf(q0.z, k0.z + e0.z, part);
        part = fmaf(q0.w, k0.w + e0.w, part);
        part = fmaf(q1.x, k1.x + e1.x, part);
        part = fmaf(q1.y, k1.y + e1.y, part);
        part = fmaf(q1.z, k1.z + e1.z, part);
        part = fmaf(q1.w, k1.w + e1.w, part);
        part += __shfl_xor_sync(gmask, part, 1);
        part += __shfl_xor_sync(gmask, part, 2);
        part += __shfl_xor_sync(gmask, part, 4);
        float alpha = part * 0.125f;  // 1/sqrt(64)

        float nm = fmaxf(m, alpha);
        float sc = __expf(m - nm);
        float w = __expf(alpha - nm);
        den = fmaf(den, sc, w);
        m = nm;

        a0.x = fmaf(a0.x, sc, w * (v0.x + e0.x));
        a0.y = fmaf(a0.y, sc, w * (v0.y + e0.y));
        a0.z = fmaf(a0.z, sc, w * (v0.z + e0.z));
        a0.w = fmaf(a0.w, sc, w * (v0.w + e0.w));
        a1.x = fmaf(a1.x, sc, w * (v1.x + e1.x));
        a1.y = fmaf(a1.y, sc, w * (v1.y + e1.y));
        a1.z = fmaf(a1.z, sc, w * (v1.z + e1.z));
        a1.w = fmaf(a1.w, sc, w * (v1.w + e1.w));
    }

    if (valid && end > start) {
        float inv = 1.f / (den + 1e-16f);
        int os = c_p2o[p];
        float* O = (os == 0) ? g_O1 : (os == 1) ? g_O2 : g_OUT2;
        float* Or = O + (size_t)d0 * 64 + lane * 8;
        redv4(Or,     a0.x * inv, a0.y * inv, a0.z * inv, a0.w * inv);
        redv4(Or + 4, a1.x * inv, a1.y * inv, a1.z * inv, a1.w * inv);
    }
}

// ---------------- final: relu(OUT2) @ lin_W + lin_b ----------------
__global__ void __launch_bounds__(256) final_kernel(
    const float* __restrict__ linW, const float* __restrict__ linb, float* __restrict__ out)
{
    __shared__ __align__(16) float4 sLW[64];
    if (threadIdx.x < 64) sLW[threadIdx.x] = *(const float4*)(linW + threadIdx.x * 4);
    __syncthreads();
    int lane = threadIdx.x & 7;
    int row = blockIdx.x * 32 + (threadIdx.x >> 3);
    if (row >= NN) return;
    const float* X = g_OUT2 + (size_t)row * 64 + lane * 8;
    float4 acc = make_float4(0.f, 0.f, 0.f, 0.f);
    #pragma unroll
    for (int c = 0; c < 8; c++) {
        float x = fmaxf(X[c], 0.f);
        float4 wv = sLW[lane * 8 + c];
        acc.x = fmaf(x, wv.x, acc.x);
        acc.y = fmaf(x, wv.y, acc.y);
        acc.z = fmaf(x, wv.z, acc.z);
        acc.w = fmaf(x, wv.w, acc.w);
    }
    #pragma unroll
    for (int off = 1; off < 8; off <<= 1) {
        acc.x += __shfl_xor_sync(0xffffffffu, acc.x, off);
        acc.y += __shfl_xor_sync(0xffffffffu, acc.y, off);
        acc.z += __shfl_xor_sync(0xffffffffu, acc.z, off);
        acc.w += __shfl_xor_sync(0xffffffffu, acc.w, off);
    }
    if (lane == 0) {
        float4 b = *(const float4*)linb;
        acc.x += b.x; acc.y += b.y; acc.z += b.z; acc.w += b.w;
        *(float4*)(out + row * 4) = acc;
    }
}

// ---------------- launcher ----------------
extern "C" void kernel_launch(void* const* d_in, const int* in_sizes, int n_in,
                              void* d_out, int out_size) {
    (void)in_sizes; (void)n_in; (void)out_size;
    const float* x0 = (const float*)d_in[0];
    const float* x1 = (const float*)d_in[1];
    const float* x2 = (const float*)d_in[2];
    const float* x3 = (const float*)d_in[3];
    const int*   EI = (const int*)d_in[4];
    const float* EA = (const float*)d_in[5];
    const float* Wq = (const float*)d_in[6];
    const float* bq = (const float*)d_in[7];
    const float* Wk = (const float*)d_in[8];
    const float* bk = (const float*)d_in[9];
    const float* Wv = (const float*)d_in[10];
    const float* bv = (const float*)d_in[11];
    const float* We = (const float*)d_in[12];
    const float* Ws = (const float*)d_in[13];
    const float* bs = (const float*)d_in[14];
    const float* lW = (const float*)d_in[15];
    const float* lb = (const float*)d_in[16];
    float* out = (float*)d_out;

    const int ROWB = (NN + 127) / 128;   // 391
    const int EB   = (NEE + 255) / 256;  // 977
    const int DB   = (NN + 31) / 32;     // 1563

    init_kernel<<<3125, 256>>>();

    // CSR build (edge_index shared by both layers)
    count_kernel<<<dim3(EB, 5), 256>>>(EI);
    scan1_kernel<<<dim3(NB, 5), 512>>>();
    scan2_kernel<<<5, 128>>>();
    scan3_kernel<<<dim3(NB, 5), 512>>>();
    scatter_kernel<<<dim3(EB, 5), 256>>>(EI);

    // ---- layer 1: 5 live edge types ----
    gemm_kernel<<<dim3(ROWB, 20), 256>>>(x0, x1, x2, x3, Wq, bq, Wk, bk, Wv, bv, Ws, bs, 0);
    fused_attn_kernel<<<dim3(DB, 5), 256>>>(EA, We, 0);

    // ---- layer 2: 3 live edge types (relu folded into gemm staging) ----
    gemm_kernel<<<dim3(ROWB, 12), 256>>>(x0, x1, x2, x3, Wq, bq, Wk, bk, Wv, bv, Ws, bs, 1);
    fused_attn_kernel<<<dim3(DB, 3), 256>>>(EA, We, 5);

    final_kernel<<<(NN + 31) / 32, 256>>>(lW, lb, out);
}